// round 15
// baseline (speedup 1.0000x reference)
#include <cuda_runtime.h>
#include <math.h>
#include <float.h>

// Problem dims
#define Bn   8
#define N1D  256
#define N2D  256
#define FD   128
#define ROWS (Bn * N1D)          // 2048
#define KD   128

#define LDT 68                   // padded minor dim of [k][*] smem tiles

// ---------------- device scratch (no allocations allowed) ----------------
__device__ float g_Mx2[Bn * N2D * FD];       // M(x2)            [2048,128]
__device__ float g_m1 [ROWS * FD];           // W(x1)            [2048,128]
__device__ float g_gh [ROWS * 3 * FD];       // x1 @ whh^T + bhh [2048,384]
__device__ float g_x  [ROWS * FD];           // relu(m1+m2)      [2048,128]
__device__ float g_gi [ROWS * 3 * FD];       // x @ wih^T + bih  [2048,384]
__device__ int   g_cnt [ROWS];               // valid-edge counts
__device__ int   g_list[ROWS * N2D];         // valid-edge j lists

// ---------------- tf32 helpers ---------------------------------------------
__device__ __forceinline__ unsigned tf32_of(float v) {
    unsigned u;
    asm("cvt.rna.tf32.f32 %0, %1;" : "=r"(u) : "f"(v));
    return u;
}

__device__ __forceinline__ void mma_tf32(float c[4],
                                         const unsigned a[4],
                                         const unsigned bf[2])
{
    asm("mma.sync.aligned.m16n8k8.row.col.f32.tf32.tf32.f32 "
        "{%0,%1,%2,%3}, {%4,%5,%6,%7}, {%8,%9}, {%0,%1,%2,%3};"
        : "+f"(c[0]), "+f"(c[1]), "+f"(c[2]), "+f"(c[3])
        : "r"(a[0]), "r"(a[1]), "r"(a[2]), "r"(a[3]),
          "r"(bf[0]), "r"(bf[1]));
}

// ---------------- 64x64 GEMM tile via tf32 tensor cores (R12 proven) -------
__device__ __forceinline__ void gemm_tile(
    const float* __restrict__ A, const float* __restrict__ W,
    const float* __restrict__ b,
    float* __restrict__ C, int ldC, int rowbase, int colbase, float* sm)
{
    unsigned* As = (unsigned*)sm;             // [KD][LDT]
    unsigned* Ws = (unsigned*)sm + KD * LDT;  // [KD][LDT]
    const int tid  = threadIdx.x;
    const int lane = tid & 31, warp = tid >> 5;
    const int kq = lane & 3;
    const int rr = lane >> 2;
    const int r  = warp * 8 + rr;     // 0..63

#pragma unroll
    for (int it = 0; it < 8; it++) {
        int kk = it * 4 + kq;
        float4 av = *(const float4*)(A + (size_t)(rowbase + r) * KD + kk * 4);
        As[(kk * 4 + 0) * LDT + r] = tf32_of(av.x);
        As[(kk * 4 + 1) * LDT + r] = tf32_of(av.y);
        As[(kk * 4 + 2) * LDT + r] = tf32_of(av.z);
        As[(kk * 4 + 3) * LDT + r] = tf32_of(av.w);
        float4 wv = *(const float4*)(W + (size_t)(colbase + r) * KD + kk * 4);
        Ws[(kk * 4 + 0) * LDT + r] = tf32_of(wv.x);
        Ws[(kk * 4 + 1) * LDT + r] = tf32_of(wv.y);
        Ws[(kk * 4 + 2) * LDT + r] = tf32_of(wv.z);
        Ws[(kk * 4 + 3) * LDT + r] = tf32_of(wv.w);
    }
    __syncthreads();

    const int g   = lane >> 2;        // 0..7
    const int tig = lane & 3;         // 0..3
    const int wrow = (warp & 1) * 32;
    const int wcol = (warp >> 1) * 16;

    float c[2][2][4];
#pragma unroll
    for (int i = 0; i < 2; i++)
#pragma unroll
        for (int j = 0; j < 2; j++)
#pragma unroll
            for (int q = 0; q < 4; q++) c[i][j][q] = 0.0f;

#pragma unroll
    for (int kb = 0; kb < KD; kb += 8) {
        const unsigned* Ak0 = As + (kb + tig) * LDT;
        const unsigned* Ak4 = Ak0 + 4 * LDT;
        const unsigned* Wk0 = Ws + (kb + tig) * LDT;
        const unsigned* Wk4 = Wk0 + 4 * LDT;

        unsigned a[2][4];
#pragma unroll
        for (int i = 0; i < 2; i++) {
            int base = wrow + i * 16 + g;
            a[i][0] = Ak0[base];
            a[i][1] = Ak0[base + 8];
            a[i][2] = Ak4[base];
            a[i][3] = Ak4[base + 8];
        }
        unsigned bf[2][2];
#pragma unroll
        for (int j = 0; j < 2; j++) {
            int base = wcol + j * 8 + g;
            bf[j][0] = Wk0[base];
            bf[j][1] = Wk4[base];
        }
#pragma unroll
        for (int i = 0; i < 2; i++)
#pragma unroll
            for (int j = 0; j < 2; j++)
                mma_tf32(c[i][j], a[i], bf[j]);
    }

#pragma unroll
    for (int i = 0; i < 2; i++) {
#pragma unroll
        for (int j = 0; j < 2; j++) {
            int col = colbase + wcol + j * 8 + 2 * tig;
            float2 bv = *(const float2*)(b + col);
            int row0 = rowbase + wrow + i * 16 + g;
            float2 o0 = make_float2(c[i][j][0] + bv.x, c[i][j][1] + bv.y);
            *(float2*)(C + (size_t)row0 * ldC + col) = o0;
            float2 o1 = make_float2(c[i][j][2] + bv.x, c[i][j][3] + bv.y);
            *(float2*)(C + (size_t)(row0 + 8) * ldC + col) = o1;
        }
    }
}

// Edge-list compaction for 8 rows (one warp per row).
__device__ __forceinline__ void lists_block(const float* __restrict__ ve, int rowblock)
{
    int w = threadIdx.x >> 5, lane = threadIdx.x & 31;
    int row = rowblock * 8 + w;
    const float* mrow = ve + (size_t)row * N2D;
    int base = 0;
#pragma unroll
    for (int r = 0; r < 8; r++) {
        int j = r * 32 + lane;
        float v = mrow[j];
        unsigned bal = __ballot_sync(0xffffffffu, v != 0.0f);
        if (v != 0.0f)
            g_list[(size_t)row * N2D + base + __popc(bal & ((1u << lane) - 1u))] = j;
        base += __popc(bal);
    }
    if (lane == 0) g_cnt[row] = base;
}

// Phase A (384 blocks): only what maskmax depends on.
//   [0,64)    Mx2  (32 row-tiles x 2 col-tiles)
//   [64,128)  m1
//   [128,384) edge lists
__global__ void __launch_bounds__(256, 3) k_pA(
    const float* __restrict__ x1, const float* __restrict__ x2,
    const float* __restrict__ ve,
    const float* __restrict__ W_w, const float* __restrict__ W_b,
    const float* __restrict__ M_w, const float* __restrict__ M_b)
{
    extern __shared__ float sm[];
    int bid = blockIdx.x;
    if (bid < 64) {
        gemm_tile(x2, M_w, M_b, g_Mx2, FD, (bid & 31) * 64, (bid >> 5) * 64, sm);
    } else if (bid < 128) {
        int t = bid - 64;
        gemm_tile(x1, W_w, W_b, g_m1, FD, (t & 31) * 64, (t >> 5) * 64, sm);
    } else {
        lists_block(ve, bid - 128);
    }
}

// Phase C (384 blocks): gi + gh GEMMs, homogeneous, one wave at occ 3.
//   [0,192)   gi = x @ wih^T + bih   (32 row-tiles x 6 col-tiles)
//   [192,384) gh = x1 @ whh^T + bhh
__global__ void __launch_bounds__(256, 3) k_pC(
    const float* __restrict__ x1,
    const float* __restrict__ wih, const float* __restrict__ bih,
    const float* __restrict__ whh, const float* __restrict__ bhh)
{
    extern __shared__ float sm[];
    int bid = blockIdx.x;
    if (bid < 192) {
        gemm_tile(g_x, wih, bih, g_gi, 3 * FD, (bid & 31) * 64, (bid >> 5) * 64, sm);
    } else {
        int t = bid - 192;
        gemm_tile(x1, whh, bhh, g_gh, 3 * FD, (t & 31) * 64, (t >> 5) * 64, sm);
    }
}

// ---------------- sparse masked max + relu(m1 + m2) — R7 proven ------------
__device__ __forceinline__ float4 max4(float4 a, float4 b) {
    float4 r;
    r.x = fmaxf(a.x, b.x); r.y = fmaxf(a.y, b.y);
    r.z = fmaxf(a.z, b.z); r.w = fmaxf(a.w, b.w);
    return r;
}

__global__ void __launch_bounds__(256) k_maskmax()
{
    int warp = threadIdx.x >> 5, lane = threadIdx.x & 31;
    int row = blockIdx.x * 8 + warp;
    int b = row >> 8;
    const float4* __restrict__ Mb = (const float4*)(g_Mx2 + (size_t)b * N2D * FD);
    const int* __restrict__ lst = g_list + (size_t)row * N2D;
    int cnt = g_cnt[row];

    float4 m = make_float4(-FLT_MAX, -FLT_MAX, -FLT_MAX, -FLT_MAX);
    int t = 0;
    for (; t + 4 <= cnt; t += 4) {
        int j0 = __ldg(lst + t),     j1 = __ldg(lst + t + 1);
        int j2 = __ldg(lst + t + 2), j3 = __ldg(lst + t + 3);
        float4 v0 = Mb[j0 * 32 + lane];
        float4 v1 = Mb[j1 * 32 + lane];
        float4 v2 = Mb[j2 * 32 + lane];
        float4 v3 = Mb[j3 * 32 + lane];
        m = max4(m, max4(max4(v0, v1), max4(v2, v3)));
    }
    for (; t < cnt; t++)
        m = max4(m, Mb[__ldg(lst + t) * 32 + lane]);
    if (cnt < N2D) {
        float4 z = make_float4(0.f, 0.f, 0.f, 0.f);
        m = max4(m, z);
    }
    float4 m1v = ((const float4*)g_m1)[row * 32 + lane];
    float4 x;
    x.x = fmaxf(m1v.x + m.x, 0.f);
    x.y = fmaxf(m1v.y + m.y, 0.f);
    x.z = fmaxf(m1v.z + m.z, 0.f);
    x.w = fmaxf(m1v.w + m.w, 0.f);
    ((float4*)g_x)[row * 32 + lane] = x;
}

// ---------------- GRU gates (tanh-only approx) -----------------------------
__device__ __forceinline__ float tanh_approx(float t) {
    float y;
    asm("tanh.approx.f32 %0, %1;" : "=f"(y) : "f"(t));
    return y;
}
__device__ __forceinline__ float sigf(float t) {
    return fmaf(tanh_approx(0.5f * t), 0.5f, 0.5f);
}

__global__ void __launch_bounds__(128) k_gates(
    const float* __restrict__ x1, float* __restrict__ out)
{
    int idx = blockIdx.x * 128 + threadIdx.x;   // one float4 (4 feats)
    int row = idx >> 5, fq = idx & 31;
    const float4* gi = (const float4*)(g_gi + (size_t)row * 384);
    const float4* gh = (const float4*)(g_gh + (size_t)row * 384);
    float4 ir = __ldg(gi + fq);
    float4 iz = __ldg(gi + 32 + fq);
    float4 in_ = __ldg(gi + 64 + fq);
    float4 hr = __ldg(gh + fq);
    float4 hz = __ldg(gh + 32 + fq);
    float4 hn = __ldg(gh + 64 + fq);
    float4 hp = __ldg((const float4*)x1 + idx);
    float4 o;
    {
        float r = sigf(ir.x + hr.x), z = sigf(iz.x + hz.x);
        float n = tanh_approx(in_.x + r * hn.x);
        o.x = (1.0f - z) * n + z * hp.x;
    }
    {
        float r = sigf(ir.y + hr.y), z = sigf(iz.y + hz.y);
        float n = tanh_approx(in_.y + r * hn.y);
        o.y = (1.0f - z) * n + z * hp.y;
    }
    {
        float r = sigf(ir.z + hr.z), z = sigf(iz.z + hz.z);
        float n = tanh_approx(in_.z + r * hn.z);
        o.z = (1.0f - z) * n + z * hp.z;
    }
    {
        float r = sigf(ir.w + hr.w), z = sigf(iz.w + hz.w);
        float n = tanh_approx(in_.w + r * hn.w);
        o.w = (1.0f - z) * n + z * hp.w;
    }
    ((float4*)out)[idx] = o;
}

// ---------------- launch ---------------------------------------------------
extern "C" void kernel_launch(void* const* d_in, const int* in_sizes, int n_in,
                              void* d_out, int out_size)
{
    const float* x1  = (const float*)d_in[0];
    const float* x2  = (const float*)d_in[1];
    const float* ve  = (const float*)d_in[2];
    const float* W_w = (const float*)d_in[3];
    const float* W_b = (const float*)d_in[4];
    const float* M_w = (const float*)d_in[5];
    const float* M_b = (const float*)d_in[6];
    const float* wih = (const float*)d_in[7];
    const float* whh = (const float*)d_in[8];
    const float* bih = (const float*)d_in[9];
    const float* bhh = (const float*)d_in[10];
    float* out = (float*)d_out;

    const int smem = 2 * KD * LDT * (int)sizeof(float);   // 69632 B
    cudaFuncSetAttribute(k_pA, cudaFuncAttributeMaxDynamicSharedMemorySize, smem);
    cudaFuncSetAttribute(k_pC, cudaFuncAttributeMaxDynamicSharedMemorySize, smem);

    k_pA<<<384, 256, smem>>>(x1, x2, ve, W_w, W_b, M_w, M_b);
    k_maskmax<<<ROWS / 8, 256>>>();
    k_pC<<<384, 256, smem>>>(x1, wih, bih, whh, bhh);
    k_gates<<<(ROWS * FD / 4) / 128, 128>>>(x1, out);
}